// round 3
// baseline (speedup 1.0000x reference)
#include <cuda_runtime.h>
#include <cstdint>

#define BB 128
#define DE 512
#define DL 256
#define G4 2048
#define TST 511

// ---------------- scratch ----------------------------------------------------
__device__ float g_z1[256 * BB * 512];
__device__ float g_z2[512 * BB * 512];
__device__ float g_gx[(size_t)TST * BB * G4];
__device__ float g_h[4][2][32 * 512];
__device__ int   g_cnt[4];

// ---------------- helpers ----------------------------------------------------
__device__ __forceinline__ float to_tf32(float x) {
    uint32_t u; asm("cvt.rna.tf32.f32 %0, %1;" : "=r"(u) : "f"(x));
    return __uint_as_float(u);
}
__device__ __forceinline__ float4 to_tf32_4(float4 v) {
    v.x = to_tf32(v.x); v.y = to_tf32(v.y); v.z = to_tf32(v.z); v.w = to_tf32(v.w);
    return v;
}
__device__ __forceinline__ uint32_t fu(float x) { return __float_as_uint(x); }

__device__ __forceinline__ void mma_tf32(float* d, const uint32_t* a, const uint32_t* b) {
    asm volatile(
        "mma.sync.aligned.m16n8k8.row.col.f32.tf32.tf32.f32 "
        "{%0,%1,%2,%3}, {%4,%5,%6,%7}, {%8,%9}, {%0,%1,%2,%3};\n"
        : "+f"(d[0]), "+f"(d[1]), "+f"(d[2]), "+f"(d[3])
        : "r"(a[0]), "r"(a[1]), "r"(a[2]), "r"(a[3]), "r"(b[0]), "r"(b[1]));
}
__device__ __forceinline__ float sigm(float x) { return 1.0f / (1.0f + __expf(-x)); }

// ---------------- upsample convs ---------------------------------------------
__global__ void upsample0(const float* __restrict__ z, const float* __restrict__ w,
                          const float* __restrict__ bias) {
    int c = threadIdx.x, t2 = blockIdx.x, b = blockIdx.y;
    int ch = ((t2 & 1) << 9) + c;
    int l = t2 >> 1;
    int ic = ch >> 2;
    float acc = bias[ch];
#pragma unroll
    for (int k = 0; k < 7; k++) {
        int li = l + k - 3;
        if (li >= 0 && li < 128)
            acc += w[ch * 7 + k] * z[((size_t)li * BB + b) * DL + ic];
    }
    g_z1[((size_t)t2 * BB + b) * 512 + c] = fmaxf(acc, 0.0f);
}

__global__ void upsample1(const float* __restrict__ w, const float* __restrict__ bias) {
    int c = threadIdx.x, t2 = blockIdx.x, b = blockIdx.y;
    int ch = ((t2 & 1) << 9) + c;
    int l = t2 >> 1;
    int ic = ch >> 1;
    float acc = bias[ch];
#pragma unroll
    for (int k = 0; k < 7; k++) {
        int li = l + k - 3;
        if (li >= 0 && li < 256)
            acc += w[ch * 7 + k] * g_z1[((size_t)li * BB + b) * 512 + ic];
    }
    g_z2[((size_t)t2 * BB + b) * 512 + c] = fmaxf(acc, 0.0f);
}

// ---------------- gates_x GEMM (tf32 mma.sync) -------------------------------
// CTA tile 128(batch) x 128(n), BK=32, 8 warps (2x4), warp 64x32.
#define GSTR 36
#define GBUF (128 * GSTR)

__global__ void __launch_bounds__(256, 1)
gates_gemm(const float* __restrict__ x, const float* __restrict__ w_ih,
           const float* __restrict__ b_ih, const float* __restrict__ b_hh) {
    extern __shared__ float sm[];
    float* As = sm;
    float* Bs = sm + 2 * GBUF;

    const int t  = blockIdx.y;
    const int n0 = blockIdx.x << 7;
    const int tid = threadIdx.x;
    const int warp = tid >> 5, lane = tid & 31;
    const int gid = lane >> 2, tg = lane & 3;
    const int wm = (warp & 1) << 6;
    const int wn = (warp >> 1) << 5;
    const int srow = tid >> 1;
    const int scol = (tid & 1) << 4;

    float acc[4][4][4];
#pragma unroll
    for (int mi = 0; mi < 4; mi++)
#pragma unroll
        for (int ni = 0; ni < 4; ni++)
#pragma unroll
            for (int cc = 0; cc < 4; cc++) acc[mi][ni][cc] = 0.0f;

    float4 a4[4], b4[4];

    auto ldg_tiles = [&](int it) {
        int kglob = it << 5;
        const float* asrc;
        if (kglob < 512)
            asrc = x + ((size_t)t * BB + srow) * DE + kglob + scol;
        else
            asrc = g_z2 + ((size_t)(t + 1) * BB + srow) * 512 + (kglob - 512) + scol;
        const float* bsrc = w_ih + (size_t)(n0 + srow) * 1024 + kglob + scol;
#pragma unroll
        for (int j = 0; j < 4; j++) {
            a4[j] = *reinterpret_cast<const float4*>(asrc + j * 4);
            b4[j] = *reinterpret_cast<const float4*>(bsrc + j * 4);
        }
    };
    auto sts_tiles = [&](int buf) {
        float* ad = As + buf * GBUF + srow * GSTR + scol;
        float* bd = Bs + buf * GBUF + srow * GSTR + scol;
#pragma unroll
        for (int j = 0; j < 4; j++) {
            *reinterpret_cast<float4*>(ad + j * 4) = to_tf32_4(a4[j]);
            *reinterpret_cast<float4*>(bd + j * 4) = to_tf32_4(b4[j]);
        }
    };

    ldg_tiles(0);
    sts_tiles(0);

    for (int it = 0; it < 32; ++it) {
        __syncthreads();
        if (it + 1 < 32) ldg_tiles(it + 1);
        const float* Ab = As + (it & 1) * GBUF;
        const float* Bb = Bs + (it & 1) * GBUF;
#pragma unroll
        for (int kk = 0; kk < 32; kk += 8) {
            uint32_t af[4][4], bf[4][2];
#pragma unroll
            for (int mi = 0; mi < 4; mi++) {
                int r = wm + mi * 16 + gid;
                af[mi][0] = fu(Ab[r * GSTR + kk + tg]);
                af[mi][1] = fu(Ab[(r + 8) * GSTR + kk + tg]);
                af[mi][2] = fu(Ab[r * GSTR + kk + tg + 4]);
                af[mi][3] = fu(Ab[(r + 8) * GSTR + kk + tg + 4]);
            }
#pragma unroll
            for (int ni = 0; ni < 4; ni++) {
                int rn = wn + ni * 8 + gid;
                bf[ni][0] = fu(Bb[rn * GSTR + kk + tg]);
                bf[ni][1] = fu(Bb[rn * GSTR + kk + tg + 4]);
            }
#pragma unroll
            for (int mi = 0; mi < 4; mi++)
#pragma unroll
                for (int ni = 0; ni < 4; ni++)
                    mma_tf32(acc[mi][ni], af[mi], bf[ni]);
        }
        if (it + 1 < 32) sts_tiles((it + 1) & 1);
    }

#pragma unroll
    for (int ni = 0; ni < 4; ni++) {
        int cb = n0 + wn + ni * 8 + 2 * tg;
        float bb0 = b_ih[cb] + b_hh[cb];
        float bb1 = b_ih[cb + 1] + b_hh[cb + 1];
#pragma unroll
        for (int mi = 0; mi < 4; mi++) {
            int r = wm + mi * 16 + gid;
            size_t base = ((size_t)t * BB + r) * G4 + cb;
            *reinterpret_cast<float2*>(g_gx + base) =
                make_float2(acc[mi][ni][0] + bb0, acc[mi][ni][1] + bb1);
            *reinterpret_cast<float2*>(g_gx + base + (size_t)8 * G4) =
                make_float2(acc[mi][ni][2] + bb0, acc[mi][ni][3] + bb1);
        }
    }
}

// ---------------- init -------------------------------------------------------
__global__ void init_state() {
    int idx = blockIdx.x * blockDim.x + threadIdx.x;
    float* hf = &g_h[0][0][0];
    for (int i = idx; i < 4 * 2 * 32 * 512; i += gridDim.x * blockDim.x) hf[i] = 0.0f;
    if (idx < 4) g_cnt[idx] = 0;
}

// ---------------- persistent LSTM scan ---------------------------------------
// grid (32 hidden-chunks, 4 batch-groups). CTA: M=32 batch, N=64 gate rows
// (16 hidden units x 4 gates, local col = gate*16+u), K=512. Weights in SMEM.
#define BSTR 516
#define HSTR 516
#define GS   72
#define SCAN_SMEM ((64 * BSTR + 32 * HSTR + 32 * GS) * 4)

__global__ void __launch_bounds__(256, 1)
lstm_scan(const float* __restrict__ w_hh, float* __restrict__ out) {
    extern __shared__ float sm[];
    float* wsm = sm;                      // [64][BSTR]
    float* hsm = sm + 64 * BSTR;          // [32][HSTR]
    float* gsm = sm + 64 * BSTR + 32 * HSTR;  // [32][GS]

    const int hc = blockIdx.x;            // hidden chunk 0..31
    const int gq = blockIdx.y;            // batch group 0..3
    const int tid = threadIdx.x;
    const int warp = tid >> 5, lane = tid & 31;
    const int gid = lane >> 2, tg = lane & 3;
    const int wm = (warp & 1) << 4;       // batch-row base 0/16
    const int wn = (warp >> 1) << 4;      // local col base 0/16/32/48

    // load w_hh slice -> smem (tf32). 64 rows x 512.
    for (int i = 0; i < 32; i++) {
        int j = tid + i * 256;            // f4 index, 8192 total
        int row = j >> 7;                 // 0..63  (128 f4 per row)
        int col = (j & 127) << 2;
        int gate = row >> 4, u = row & 15;
        const float4 v = *reinterpret_cast<const float4*>(
            w_hh + ((size_t)(gate * 512 + hc * 16 + u)) * 512 + col);
        *reinterpret_cast<float4*>(wsm + row * BSTR + col) = to_tf32_4(v);
    }
    __syncthreads();

    const int b0 = tid >> 4;              // epilogue pair 0: batch row
    const int uu = tid & 15;              // hidden unit within chunk
    float c0 = 0.0f, c1 = 0.0f;           // cell state (pairs tid, tid+256)
    volatile int* cnt = &g_cnt[gq];

    for (int t = 0; t < TST; t++) {
        const int p = t & 1;

        // prefetch gx for this step (8 scattered coalesced loads)
        size_t gxb0 = ((size_t)t * BB + gq * 32 + b0) * G4 + hc * 16 + uu;
        size_t gxb1 = gxb0 + (size_t)16 * G4;
        float xi0 = __ldcs(g_gx + gxb0),        xi1 = __ldcs(g_gx + gxb1);
        float xf0 = __ldcs(g_gx + gxb0 + 512),  xf1 = __ldcs(g_gx + gxb1 + 512);
        float xg0 = __ldcs(g_gx + gxb0 + 1024), xg1 = __ldcs(g_gx + gxb1 + 1024);
        float xo0 = __ldcs(g_gx + gxb0 + 1536), xo1 = __ldcs(g_gx + gxb1 + 1536);

        // load group h (L2, bypass L1) -> smem tf32
        const float4* hg = reinterpret_cast<const float4*>(g_h[gq][p]);
#pragma unroll
        for (int i = 0; i < 16; i++) {
            int j = tid + i * 256;        // 4096 f4
            float4 v = __ldcg(hg + j);
            int row = j >> 7, col = (j & 127) << 2;
            *reinterpret_cast<float4*>(hsm + row * HSTR + col) = to_tf32_4(v);
        }
        __syncthreads();

        // gates_h = h @ w_hh_slice^T : warp tile 16x16
        float acc0[4] = {0.f, 0.f, 0.f, 0.f};
        float acc1[4] = {0.f, 0.f, 0.f, 0.f};
        const int r = wm + gid;
        const int rn0 = wn + gid, rn1 = wn + 8 + gid;
#pragma unroll 8
        for (int k0 = 0; k0 < 512; k0 += 8) {
            uint32_t a[4], bA[2], bB[2];
            a[0] = fu(hsm[r * HSTR + k0 + tg]);
            a[1] = fu(hsm[(r + 8) * HSTR + k0 + tg]);
            a[2] = fu(hsm[r * HSTR + k0 + tg + 4]);
            a[3] = fu(hsm[(r + 8) * HSTR + k0 + tg + 4]);
            bA[0] = fu(wsm[rn0 * BSTR + k0 + tg]);
            bA[1] = fu(wsm[rn0 * BSTR + k0 + tg + 4]);
            bB[0] = fu(wsm[rn1 * BSTR + k0 + tg]);
            bB[1] = fu(wsm[rn1 * BSTR + k0 + tg + 4]);
            mma_tf32(acc0, a, bA);
            mma_tf32(acc1, a, bB);
        }

        // acc -> gsm [batch][local col]
        {
            int col = wn + 2 * tg;
            gsm[(wm + gid) * GS + col]     = acc0[0];
            gsm[(wm + gid) * GS + col + 1] = acc0[1];
            gsm[(wm + gid + 8) * GS + col]     = acc0[2];
            gsm[(wm + gid + 8) * GS + col + 1] = acc0[3];
            gsm[(wm + gid) * GS + col + 8]     = acc1[0];
            gsm[(wm + gid) * GS + col + 9]     = acc1[1];
            gsm[(wm + gid + 8) * GS + col + 8] = acc1[2];
            gsm[(wm + gid + 8) * GS + col + 9] = acc1[3];
        }
        __syncthreads();

        // epilogue: two (b,u) pairs per thread
        float* hout = g_h[gq][p ^ 1];
        size_t ob = (size_t)t * (BB * DE) + (size_t)(gq * 32 + b0) * DE + hc * 16 + uu;
        {
            float gi = gsm[b0 * GS + uu]      + xi0;
            float gf = gsm[b0 * GS + 16 + uu] + xf0;
            float gg = gsm[b0 * GS + 32 + uu] + xg0;
            float go = gsm[b0 * GS + 48 + uu] + xo0;
            c0 = sigm(gf) * c0 + sigm(gi) * tanhf(gg);
            float h = sigm(go) * tanhf(c0);
            hout[b0 * 512 + hc * 16 + uu] = h;
            out[ob] = h;
        }
        {
            int b1r = b0 + 16;
            float gi = gsm[b1r * GS + uu]      + xi1;
            float gf = gsm[b1r * GS + 16 + uu] + xf1;
            float gg = gsm[b1r * GS + 32 + uu] + xg1;
            float go = gsm[b1r * GS + 48 + uu] + xo1;
            c1 = sigm(gf) * c1 + sigm(gi) * tanhf(gg);
            float h = sigm(go) * tanhf(c1);
            hout[b1r * 512 + hc * 16 + uu] = h;
            out[ob + (size_t)16 * DE] = h;
        }

        // group barrier (32 CTAs)
        __threadfence();
        __syncthreads();
        if (tid == 0) {
            atomicAdd((int*)cnt, 1);
            int target = 32 * (t + 1);
            while (*cnt < target) { }
            __threadfence();
        }
        __syncthreads();
    }
}

// ---------------- launch ------------------------------------------------------
extern "C" void kernel_launch(void* const* d_in, const int* in_sizes, int n_in,
                              void* d_out, int out_size) {
    const float* x       = (const float*)d_in[0];
    const float* z       = (const float*)d_in[1];
    const float* conv0_w = (const float*)d_in[2];
    const float* conv0_b = (const float*)d_in[3];
    const float* conv1_w = (const float*)d_in[4];
    const float* conv1_b = (const float*)d_in[5];
    const float* w_ih    = (const float*)d_in[6];
    const float* w_hh    = (const float*)d_in[7];
    const float* b_ih    = (const float*)d_in[8];
    const float* b_hh    = (const float*)d_in[9];
    float* out = (float*)d_out;

    static bool attr_done = false;
    if (!attr_done) {
        cudaFuncSetAttribute(gates_gemm, cudaFuncAttributeMaxDynamicSharedMemorySize,
                             4 * GBUF * 4);
        cudaFuncSetAttribute(lstm_scan, cudaFuncAttributeMaxDynamicSharedMemorySize,
                             SCAN_SMEM);
        attr_done = true;
    }

    init_state<<<64, 512>>>();
    upsample0<<<dim3(256, 128), 512>>>(z, conv0_w, conv0_b);
    upsample1<<<dim3(512, 128), 512>>>(conv1_w, conv1_b);
    gates_gemm<<<dim3(16, TST), 256, 4 * GBUF * 4>>>(x, w_ih, b_ih, b_hh);
    lstm_scan<<<dim3(32, 4), 256, SCAN_SMEM>>>(w_hh, out);
}

// round 4
// speedup vs baseline: 1.0242x; 1.0242x over previous
#include <cuda_runtime.h>
#include <cstdint>

#define BB 128
#define DE 512
#define DL 256
#define G4 2048
#define TST 511

// ---------------- scratch ----------------------------------------------------
__device__ float g_z1[256 * BB * 512];
__device__ float g_z2[512 * BB * 512];
__device__ float g_gx[(size_t)TST * BB * G4];
__device__ float g_h[4][2][32 * 512];
__device__ int   g_cnt[4];

// ---------------- helpers ----------------------------------------------------
__device__ __forceinline__ float to_tf32(float x) {
    uint32_t u; asm("cvt.rna.tf32.f32 %0, %1;" : "=r"(u) : "f"(x));
    return __uint_as_float(u);
}
__device__ __forceinline__ float4 to_tf32_4(float4 v) {
    v.x = to_tf32(v.x); v.y = to_tf32(v.y); v.z = to_tf32(v.z); v.w = to_tf32(v.w);
    return v;
}

__device__ __forceinline__ void mma_tf32(float* d, const uint32_t* a, const uint32_t* b) {
    asm volatile(
        "mma.sync.aligned.m16n8k8.row.col.f32.tf32.tf32.f32 "
        "{%0,%1,%2,%3}, {%4,%5,%6,%7}, {%8,%9}, {%0,%1,%2,%3};\n"
        : "+f"(d[0]), "+f"(d[1]), "+f"(d[2]), "+f"(d[3])
        : "r"(a[0]), "r"(a[1]), "r"(a[2]), "r"(a[3]), "r"(b[0]), "r"(b[1]));
}
__device__ __forceinline__ float sigm(float x) { return 1.0f / (1.0f + __expf(-x)); }

// fragment-chunk sizes (floats), padded for bank-conflict-free access
#define ACH 148   // A chunk: 32 lanes * 4 + pads
#define BCH 66    // B chunk: 32 lanes * 2 + pads

// ---------------- upsample convs ---------------------------------------------
__global__ void upsample0(const float* __restrict__ z, const float* __restrict__ w,
                          const float* __restrict__ bias) {
    int c = threadIdx.x, t2 = blockIdx.x, b = blockIdx.y;
    int ch = ((t2 & 1) << 9) + c;
    int l = t2 >> 1;
    int ic = ch >> 2;
    float acc = bias[ch];
#pragma unroll
    for (int k = 0; k < 7; k++) {
        int li = l + k - 3;
        if (li >= 0 && li < 128)
            acc += w[ch * 7 + k] * z[((size_t)li * BB + b) * DL + ic];
    }
    g_z1[((size_t)t2 * BB + b) * 512 + c] = fmaxf(acc, 0.0f);
}

__global__ void upsample1(const float* __restrict__ w, const float* __restrict__ bias) {
    int c = threadIdx.x, t2 = blockIdx.x, b = blockIdx.y;
    int ch = ((t2 & 1) << 9) + c;
    int l = t2 >> 1;
    int ic = ch >> 1;
    float acc = bias[ch];
#pragma unroll
    for (int k = 0; k < 7; k++) {
        int li = l + k - 3;
        if (li >= 0 && li < 256)
            acc += w[ch * 7 + k] * g_z1[((size_t)li * BB + b) * 512 + ic];
    }
    g_z2[((size_t)t2 * BB + b) * 512 + c] = fmaxf(acc, 0.0f);
}

// ---------------- gates_x GEMM (tf32 mma.sync, fragment-major smem) ----------
// CTA tile 128(batch) x 128(n), BK=32, 8 warps (2x4), warp 64x32.
#define ABUF_G (8 * 4 * ACH)    // 4736 floats per buffer
#define BBUF_G (16 * 4 * BCH)   // 4224 floats per buffer
#define GEMM_SMEM ((2 * ABUF_G + 2 * BBUF_G) * 4)

__global__ void __launch_bounds__(256, 1)
gates_gemm(const float* __restrict__ x, const float* __restrict__ w_ih,
           const float* __restrict__ b_ih, const float* __restrict__ b_hh) {
    extern __shared__ float sm[];
    float* As = sm;                  // [2][8 rb][4 kc][ACH]
    float* Bs = sm + 2 * ABUF_G;     // [2][16 cb][4 kc][BCH]

    const int t  = blockIdx.y;
    const int n0 = blockIdx.x << 7;
    const int tid = threadIdx.x;
    const int warp = tid >> 5, lane = tid & 31;
    const int gid = lane >> 2, tg = lane & 3;
    const int wmr = warp & 1;        // A row-block base = wmr*4
    const int wnq = warp >> 1;       // B col-block base = wnq*4
    const int srow = tid >> 1;
    const int scol = (tid & 1) << 4;

    // store-side constants
    const int rb_s = srow >> 4, gidr = srow & 7, half = (srow >> 3) & 1;
    const int cb_s = srow >> 3, gidn = srow & 7;
    const int abase_s = (gidr << 4) + ((gidr >> 1) << 2);  // lane*4 + pad
    const int bbase_s = (gidn << 3) + ((gidn >> 2) << 1);  // lane*2 + pad
    // load-side fragment offsets
    const int aoff = (lane << 2) + ((lane >> 3) << 2);
    const int boff = (lane << 1) + ((lane >> 4) << 1);

    float acc[4][4][4];
#pragma unroll
    for (int mi = 0; mi < 4; mi++)
#pragma unroll
        for (int ni = 0; ni < 4; ni++)
#pragma unroll
            for (int cc = 0; cc < 4; cc++) acc[mi][ni][cc] = 0.0f;

    float4 a4[4], b4[4];

    auto ldg_tiles = [&](int it) {
        int kglob = it << 5;
        const float* asrc;
        if (kglob < 512)
            asrc = x + ((size_t)t * BB + srow) * DE + kglob + scol;
        else
            asrc = g_z2 + ((size_t)(t + 1) * BB + srow) * 512 + (kglob - 512) + scol;
        const float* bsrc = w_ih + (size_t)(n0 + srow) * 1024 + kglob + scol;
#pragma unroll
        for (int j = 0; j < 4; j++) {
            a4[j] = *reinterpret_cast<const float4*>(asrc + j * 4);
            b4[j] = *reinterpret_cast<const float4*>(bsrc + j * 4);
        }
    };
    auto sts_tiles = [&](int buf) {
        float* Ad = As + buf * ABUF_G;
        float* Bd = Bs + buf * BBUF_G;
#pragma unroll
        for (int j = 0; j < 4; j++) {
            int kc = (scol >> 3) + (j >> 1);
            int khalf = j & 1;
            const float* ap = reinterpret_cast<const float*>(&a4[j]);
            const float* bp = reinterpret_cast<const float*>(&b4[j]);
            float* adst = Ad + (rb_s * 4 + kc) * ACH + abase_s + half + (khalf << 1);
            float* bdst = Bd + (cb_s * 4 + kc) * BCH + bbase_s + khalf;
#pragma unroll
            for (int s = 0; s < 4; s++) {
                adst[s << 2] = to_tf32(ap[s]);
                bdst[s << 1] = to_tf32(bp[s]);
            }
        }
    };

    ldg_tiles(0);
    sts_tiles(0);

    for (int it = 0; it < 32; ++it) {
        __syncthreads();
        if (it + 1 < 32) ldg_tiles(it + 1);
        const float* Ab = As + (it & 1) * ABUF_G;
        const float* Bb = Bs + (it & 1) * BBUF_G;
#pragma unroll
        for (int kc = 0; kc < 4; kc++) {
            float4 av[4]; float2 bv[4];
#pragma unroll
            for (int mi = 0; mi < 4; mi++)
                av[mi] = *reinterpret_cast<const float4*>(
                    Ab + ((wmr * 4 + mi) * 4 + kc) * ACH + aoff);
#pragma unroll
            for (int ni = 0; ni < 4; ni++)
                bv[ni] = *reinterpret_cast<const float2*>(
                    Bb + ((wnq * 4 + ni) * 4 + kc) * BCH + boff);
#pragma unroll
            for (int mi = 0; mi < 4; mi++)
#pragma unroll
                for (int ni = 0; ni < 4; ni++)
                    mma_tf32(acc[mi][ni],
                             reinterpret_cast<const uint32_t*>(&av[mi]),
                             reinterpret_cast<const uint32_t*>(&bv[ni]));
        }
        if (it + 1 < 32) sts_tiles((it + 1) & 1);
    }

    // epilogue
    const int ewm = (warp & 1) << 6;
    const int ewn = (warp >> 1) << 5;
#pragma unroll
    for (int ni = 0; ni < 4; ni++) {
        int cb = n0 + ewn + ni * 8 + 2 * tg;
        float bb0 = b_ih[cb] + b_hh[cb];
        float bb1 = b_ih[cb + 1] + b_hh[cb + 1];
#pragma unroll
        for (int mi = 0; mi < 4; mi++) {
            int r = ewm + mi * 16 + gid;
            size_t base = ((size_t)t * BB + r) * G4 + cb;
            *reinterpret_cast<float2*>(g_gx + base) =
                make_float2(acc[mi][ni][0] + bb0, acc[mi][ni][1] + bb1);
            *reinterpret_cast<float2*>(g_gx + base + (size_t)8 * G4) =
                make_float2(acc[mi][ni][2] + bb0, acc[mi][ni][3] + bb1);
        }
    }
}

// ---------------- init -------------------------------------------------------
__global__ void init_state() {
    int idx = blockIdx.x * blockDim.x + threadIdx.x;
    float* hf = &g_h[0][0][0];
    for (int i = idx; i < 4 * 2 * 32 * 512; i += gridDim.x * blockDim.x) hf[i] = 0.0f;
    if (idx < 4) g_cnt[idx] = 0;
}

// ---------------- persistent LSTM scan ---------------------------------------
// grid (32 hidden-chunks, 4 batch-groups). CTA: M=32 batch, N=64 gate rows,
// K=512. Weights tf32 fragment-major in SMEM.
#define WSM_F (8 * 64 * BCH)        // 33792 floats
#define HSM_F (2 * 64 * ACH)        // 18944 floats
#define GS    72
#define SCAN_SMEM ((WSM_F + HSM_F + 32 * GS) * 4)

__global__ void __launch_bounds__(256, 1)
lstm_scan(const float* __restrict__ w_hh, float* __restrict__ out) {
    extern __shared__ float sm[];
    float* wsm = sm;                    // [8 cb][64 kc][BCH]
    float* hsm = sm + WSM_F;            // [2 rb][64 kc][ACH]
    float* gsm = sm + WSM_F + HSM_F;    // [32][GS]

    const int hc = blockIdx.x;          // hidden chunk 0..31
    const int gq = blockIdx.y;          // batch group 0..3
    const int tid = threadIdx.x;
    const int warp = tid >> 5, lane = tid & 31;
    const int gid = lane >> 2, tg = lane & 3;
    const int wm = (warp & 1) << 4;     // batch-row base 0/16
    const int wn = (warp >> 1) << 4;    // local col base 0/16/32/48

    const int aoff = (lane << 2) + ((lane >> 3) << 2);
    const int boff = (lane << 1) + ((lane >> 4) << 1);

    // load w_hh slice -> fragment-major smem (tf32). 64 rows x 512 k.
    for (int i = 0; i < 32; i++) {
        int j = tid + i * 256;          // f4 index, 8192 total
        int row = j >> 7;               // local col n 0..63 (gate*16+u)
        int kq = j & 127;
        int kc = kq >> 1, khalf = kq & 1;
        int gate = row >> 4, u = row & 15;
        float4 v = to_tf32_4(*reinterpret_cast<const float4*>(
            w_hh + (size_t)(gate * 512 + hc * 16 + u) * 512 + (kq << 2)));
        int cb = row >> 3, gw = row & 7;
        float* dst = wsm + (cb * 64 + kc) * BCH + (gw << 3) + ((gw >> 2) << 1) + khalf;
        const float* vp = reinterpret_cast<const float*>(&v);
#pragma unroll
        for (int s = 0; s < 4; s++) dst[s << 1] = vp[s];
    }
    __syncthreads();

    const int rb = warp & 1;
    const int cb0 = (warp >> 1) << 1, cb1 = cb0 + 1;
    const float* Abase = hsm + rb * 64 * ACH + aoff;
    const float* B0 = wsm + cb0 * 64 * BCH + boff;
    const float* B1 = wsm + cb1 * 64 * BCH + boff;

    const int b0 = tid >> 4;            // epilogue: batch row
    const int uu = tid & 15;            // hidden unit within chunk
    float c0 = 0.0f, c1 = 0.0f;
    volatile int* cnt = &g_cnt[gq];

    for (int t = 0; t < TST; t++) {
        const int p = t & 1;

        // prefetch gx for this step
        size_t gxb0 = ((size_t)t * BB + gq * 32 + b0) * G4 + hc * 16 + uu;
        size_t gxb1 = gxb0 + (size_t)16 * G4;
        float xi0 = __ldcs(g_gx + gxb0),        xi1 = __ldcs(g_gx + gxb1);
        float xf0 = __ldcs(g_gx + gxb0 + 512),  xf1 = __ldcs(g_gx + gxb1 + 512);
        float xg0 = __ldcs(g_gx + gxb0 + 1024), xg1 = __ldcs(g_gx + gxb1 + 1024);
        float xo0 = __ldcs(g_gx + gxb0 + 1536), xo1 = __ldcs(g_gx + gxb1 + 1536);

        // load group h (L2) -> fragment-major smem (tf32)
        const float4* hg = reinterpret_cast<const float4*>(g_h[gq][p]);
#pragma unroll
        for (int i = 0; i < 16; i++) {
            int j = tid + i * 256;      // 4096 f4
            float4 v = __ldcg(hg + j);
            int row = j >> 7;           // 0..31
            int kq = j & 127;
            int kc = kq >> 1, khalf = kq & 1;
            int rbw = row >> 4, r16 = row & 15;
            int gh = r16 & 7, hh = r16 >> 3;
            float* dst = hsm + (rbw * 64 + kc) * ACH + (gh << 4) + ((gh >> 1) << 2)
                         + hh + (khalf << 1);
            dst[0]  = to_tf32(v.x);
            dst[4]  = to_tf32(v.y);
            dst[8]  = to_tf32(v.z);
            dst[12] = to_tf32(v.w);
        }
        __syncthreads();

        // gates_h = h @ w_hh_slice^T : 3 LDS + 2 HMMA per k-chunk
        float acc0[4] = {0.f, 0.f, 0.f, 0.f};
        float acc1[4] = {0.f, 0.f, 0.f, 0.f};
#pragma unroll 8
        for (int kc = 0; kc < 64; kc++) {
            float4 av = *reinterpret_cast<const float4*>(Abase + kc * ACH);
            float2 b0v = *reinterpret_cast<const float2*>(B0 + kc * BCH);
            float2 b1v = *reinterpret_cast<const float2*>(B1 + kc * BCH);
            mma_tf32(acc0, reinterpret_cast<const uint32_t*>(&av),
                           reinterpret_cast<const uint32_t*>(&b0v));
            mma_tf32(acc1, reinterpret_cast<const uint32_t*>(&av),
                           reinterpret_cast<const uint32_t*>(&b1v));
        }

        // acc -> gsm [batch][local col]
        {
            int col = wn + 2 * tg;
            gsm[(wm + gid) * GS + col]         = acc0[0];
            gsm[(wm + gid) * GS + col + 1]     = acc0[1];
            gsm[(wm + gid + 8) * GS + col]     = acc0[2];
            gsm[(wm + gid + 8) * GS + col + 1] = acc0[3];
            gsm[(wm + gid) * GS + col + 8]     = acc1[0];
            gsm[(wm + gid) * GS + col + 9]     = acc1[1];
            gsm[(wm + gid + 8) * GS + col + 8] = acc1[2];
            gsm[(wm + gid + 8) * GS + col + 9] = acc1[3];
        }
        __syncthreads();

        // epilogue: two (b,u) pairs per thread
        float* hout = g_h[gq][p ^ 1];
        size_t ob = (size_t)t * (BB * DE) + (size_t)(gq * 32 + b0) * DE + hc * 16 + uu;
        {
            float gi = gsm[b0 * GS + uu]      + xi0;
            float gf = gsm[b0 * GS + 16 + uu] + xf0;
            float gg = gsm[b0 * GS + 32 + uu] + xg0;
            float go = gsm[b0 * GS + 48 + uu] + xo0;
            c0 = sigm(gf) * c0 + sigm(gi) * tanhf(gg);
            float h = sigm(go) * tanhf(c0);
            hout[b0 * 512 + hc * 16 + uu] = h;
            out[ob] = h;
        }
        {
            int b1r = b0 + 16;
            float gi = gsm[b1r * GS + uu]      + xi1;
            float gf = gsm[b1r * GS + 16 + uu] + xf1;
            float gg = gsm[b1r * GS + 32 + uu] + xg1;
            float go = gsm[b1r * GS + 48 + uu] + xo1;
            c1 = sigm(gf) * c1 + sigm(gi) * tanhf(gg);
            float h = sigm(go) * tanhf(c1);
            hout[b1r * 512 + hc * 16 + uu] = h;
            out[ob + (size_t)16 * DE] = h;
        }

        // group barrier (32 CTAs)
        __threadfence();
        __syncthreads();
        if (tid == 0) {
            atomicAdd((int*)cnt, 1);
            int target = 32 * (t + 1);
            while (*cnt < target) { }
            __threadfence();
        }
        __syncthreads();
    }
}

// ---------------- launch ------------------------------------------------------
extern "C" void kernel_launch(void* const* d_in, const int* in_sizes, int n_in,
                              void* d_out, int out_size) {
    const float* x       = (const float*)d_in[0];
    const float* z       = (const float*)d_in[1];
    const float* conv0_w = (const float*)d_in[2];
    const float* conv0_b = (const float*)d_in[3];
    const float* conv1_w = (const float*)d_in[4];
    const float* conv1_b = (const float*)d_in[5];
    const float* w_ih    = (const float*)d_in[6];
    const float* w_hh    = (const float*)d_in[7];
    const float* b_ih    = (const float*)d_in[8];
    const float* b_hh    = (const float*)d_in[9];
    float* out = (float*)d_out;

    static bool attr_done = false;
    if (!attr_done) {
        cudaFuncSetAttribute(gates_gemm, cudaFuncAttributeMaxDynamicSharedMemorySize,
                             GEMM_SMEM);
        cudaFuncSetAttribute(lstm_scan, cudaFuncAttributeMaxDynamicSharedMemorySize,
                             SCAN_SMEM);
        attr_done = true;
    }

    init_state<<<64, 512>>>();
    upsample0<<<dim3(256, 128), 512>>>(z, conv0_w, conv0_b);
    upsample1<<<dim3(512, 128), 512>>>(conv1_w, conv1_b);
    gates_gemm<<<dim3(16, TST), 256, GEMM_SMEM>>>(x, w_ih, b_ih, b_hh);
    lstm_scan<<<dim3(32, 4), 256, SCAN_SMEM>>>(w_hh, out);
}